// round 14
// baseline (speedup 1.0000x reference)
#include <cuda_runtime.h>
#include <cuda_fp16.h>
#include <math.h>
#include <stdint.h>

// ---------------- problem constants ----------------
#define IMW   256
#define HWIMG 65536          // 256*256
#define BDIM  2
#define CDIM  96
#define C6    576            // 6*DIM
#define C2    192            // 2*DIM
#define CHID  255            // hidden_features
#define CHID2 510            // 2*hidden
#define HEADS 4
#define CH    48             // channels per head
#define NF    33             // rfft bins of 64

// ---------------- scratch (fp16 intermediates) ----------------
__device__ __half g_h1 [(size_t)BDIM * C6    * HWIMG];
__device__ __half g_h2 [(size_t)BDIM * C6    * HWIMG];
__device__ __half g_att[(size_t)BDIM * C2    * HWIMG];
__device__ float  g_x1 [(size_t)BDIM * CDIM  * HWIMG];
__device__ __half g_x1h[(size_t)BDIM * CDIM  * HWIMG];
__device__ __half g_f1 [(size_t)BDIM * CHID2 * HWIMG];
__device__ __half g_g  [(size_t)BDIM * CHID  * HWIMG];
__device__ float  g_inv[(size_t)BDIM * HWIMG];
__device__ uint32_t g_dft[64 * 84];   // Ds[n][2f]=cos, [2f+1]=-sin, cols>=66 zero

__device__ __forceinline__ uint32_t f2tf(float f) {
    uint32_t u;
    asm("cvt.rna.tf32.f32 %0, %1;" : "=r"(u) : "f"(f));
    return u;
}
__device__ __forceinline__ uint32_t fneg(uint32_t u) { return u ^ 0x80000000u; }
__device__ __forceinline__ uint32_t h2tf(__half h) {
    return __float_as_uint(__half2float(h));
}

__device__ __forceinline__ void mma_tf32(float* d, uint32_t a0, uint32_t a1,
                                         uint32_t a2, uint32_t a3,
                                         uint32_t b0, uint32_t b1) {
    asm volatile(
        "mma.sync.aligned.m16n8k8.row.col.f32.tf32.tf32.f32 "
        "{%0,%1,%2,%3}, {%4,%5,%6,%7}, {%8,%9}, {%0,%1,%2,%3};\n"
        : "+f"(d[0]), "+f"(d[1]), "+f"(d[2]), "+f"(d[3])
        : "r"(a0), "r"(a1), "r"(a2), "r"(a3), "r"(b0), "r"(b1));
}

__device__ __forceinline__ void cp_async16(uint32_t smem_addr, const void* gptr) {
    asm volatile("cp.async.cg.shared.global [%0], [%1], 16;\n"
                 :: "r"(smem_addr), "l"(gptr));
}

// ---------------- twiddle init ----------------
__global__ void dft_init_kernel() {
    int i = blockIdx.x * 256 + threadIdx.x;
    if (i >= 64 * 84) return;
    int n = i / 84, col = i % 84, f = col >> 1;
    float v = 0.f;
    if (col < 66) {
        float ang = 6.2831853071795864f * (float)((f * n) & 63) / 64.f;
        v = (col & 1) ? -sinf(ang) : cosf(ang);
    }
    g_dft[i] = f2tf(v);
}

// ---------------- LN scale only ----------------
__global__ void ln_scale_kernel(const float* __restrict__ x, float* __restrict__ inv) {
    int pix = blockIdx.x * 256 + threadIdx.x;
    int b   = blockIdx.y;
    const float* xb = x + (size_t)b * CDIM * HWIMG + pix;
    float s = 0.f, s2 = 0.f;
    #pragma unroll 8
    for (int c = 0; c < CDIM; c++) {
        float v = xb[(size_t)c * HWIMG];
        s += v; s2 += v * v;
    }
    float mean = s * (1.0f / CDIM);
    float var  = s2 * (1.0f / CDIM) - mean * mean;
    inv[(size_t)b * HWIMG + pix] = rsqrtf(var + 1e-5f);
}

// ---------------- tf32 conv1x1 GEMM: cp.async + ldmatrix A-fragments ----------------
#define GBM 128
#define GBN 128
#define GBK 32
#define ASP 36               // A pitch [m][k]: rows 144B (16B-aligned), 4i%32 distinct
#define GP  136              // B pitch [k][n]
#define ASM(st,m,k) Asb[(((st) * GBM) + (m)) * ASP + (k)]
#define BS(st,k,n)  Bsb[((st) * GBK + (k)) * GP + (n)]
#define BSH(st,k,n) BsbH[((st) * GBK + (k)) * GP + (n)]
#define A_FLOATS (2 * GBM * ASP)                 // 9216
#define GEMM_SMEM_BYTES ((A_FLOATS + 2 * GBK * GP) * 4)   // 71680

template<bool RESID, bool XHALF>
__global__ void __launch_bounds__(256) gemm_tf32_kernel(
        const float* __restrict__ A, const void* __restrict__ Xv,
        const float* __restrict__ R, const float* __restrict__ nw,
        const float* __restrict__ cs, float* __restrict__ Yf,
        __half* __restrict__ Yh, int M, int K) {
    extern __shared__ uint32_t gsm[];
    uint32_t* Asb  = gsm;
    uint32_t* Bsb  = gsm + A_FLOATS;
    __half*   BsbH = (__half*)Bsb;

    int tid  = threadIdx.x;
    int warp = tid >> 5, lane = tid & 31;
    int g    = lane >> 2, tg = lane & 3;
    int wm   = (warp & 1) * 64;
    int wn   = (warp >> 1) * 32;

    int bn = blockIdx.x * GBN;
    int bm = blockIdx.y * GBM;
    int b  = blockIdx.z;
    const float*  Xf = XHALF ? nullptr : ((const float*)Xv + (size_t)b * K * HWIMG + bn);
    const __half* Xh = XHALF ? ((const __half*)Xv + (size_t)b * K * HWIMG + bn) : nullptr;

    // ldmatrix per-lane address pieces: matrix = lane>>3
    int aRow = wm + ((lane >> 3) & 1) * 8 + (lane & 7);  // + mt*16 later
    int aCol = (lane >> 4) * 4;                          // + kb later
    uint32_t asbase = (uint32_t)__cvta_generic_to_shared(Asb);

    float acc[4][4][4];
    #pragma unroll
    for (int mt = 0; mt < 4; mt++)
        #pragma unroll
        for (int nt = 0; nt < 4; nt++)
            #pragma unroll
            for (int i = 0; i < 4; i++) acc[mt][nt][i] = 0.f;

    int xk  = tid >> 3;
    int xc  = (tid & 7) * 4;      // fp32 path
    int xch = (tid & 7) * 16;     // fp16 path
    int nIter = (K + GBK - 1) / GBK;

    auto loadTiles = [&](int it, int st) {
        int k0 = it * GBK;
        #pragma unroll
        for (int i = 0; i < 16; i++) {
            int lin = tid + i * 256;
            int m = lin & 127, k = lin >> 7;
            int gm = bm + m, gk = k0 + k;
            float v = (gm < M && gk < K) ? A[(size_t)gm * K + gk] : 0.f;
            if (nw && gk < K) v *= nw[gk];
            ASM(st, m, k) = f2tf(v);
        }
        int gk = k0 + xk;
        if (XHALF) {
            if (gk < K) {
                const __half* p = Xh + (size_t)gk * HWIMG + xch;
                uint32_t sa = (uint32_t)__cvta_generic_to_shared(&BSH(st, xk, xch));
                cp_async16(sa, p);
                cp_async16(sa + 16, p + 8);
            } else {
                uint4 z = make_uint4(0u, 0u, 0u, 0u);
                *(uint4*)&BSH(st, xk, xch)     = z;
                *(uint4*)&BSH(st, xk, xch + 8) = z;
            }
        } else {
            if (gk < K) {
                const float* p = Xf + (size_t)gk * HWIMG + xc;
                uint32_t sa = (uint32_t)__cvta_generic_to_shared(&BS(st, xk, xc));
                #pragma unroll
                for (int j = 0; j < 4; j++)
                    cp_async16(sa + j * 128, p + j * 32);
            } else {
                uint4 z = make_uint4(0u, 0u, 0u, 0u);
                #pragma unroll
                for (int j = 0; j < 4; j++)
                    *(uint4*)&BS(st, xk, xc + j * 32) = z;
            }
        }
    };

    loadTiles(0, 0);
    asm volatile("cp.async.commit_group;\n" ::: "memory");

    for (int it = 0; it < nIter; it++) {
        int st = it & 1;
        if (it + 1 < nIter) {
            loadTiles(it + 1, st ^ 1);
            asm volatile("cp.async.commit_group;\n" ::: "memory");
            asm volatile("cp.async.wait_group 1;\n" ::: "memory");
        } else {
            asm volatile("cp.async.wait_group 0;\n" ::: "memory");
        }
        __syncthreads();

        uint32_t stBase = asbase + (uint32_t)(st * GBM * ASP * 4);
        #pragma unroll
        for (int ks = 0; ks < 4; ks++) {
            int kb = ks * 8;
            uint32_t af[4][4], bf[4][2];
            #pragma unroll
            for (int mt = 0; mt < 4; mt++) {
                uint32_t addr = stBase +
                    (uint32_t)(((aRow + mt * 16) * ASP + aCol + kb) * 4);
                asm volatile(
                    "ldmatrix.sync.aligned.m8n8.x4.shared.b16 {%0,%1,%2,%3}, [%4];\n"
                    : "=r"(af[mt][0]), "=r"(af[mt][1]),
                      "=r"(af[mt][2]), "=r"(af[mt][3])
                    : "r"(addr));
            }
            #pragma unroll
            for (int nt = 0; nt < 4; nt++) {
                int n0 = wn + nt * 8;
                if (XHALF) {
                    bf[nt][0] = h2tf(BSH(st, kb + tg,     n0 + g));
                    bf[nt][1] = h2tf(BSH(st, kb + tg + 4, n0 + g));
                } else {
                    bf[nt][0] = BS(st, kb + tg,     n0 + g);
                    bf[nt][1] = BS(st, kb + tg + 4, n0 + g);
                }
            }
            #pragma unroll
            for (int mt = 0; mt < 4; mt++)
                #pragma unroll
                for (int nt = 0; nt < 4; nt++)
                    mma_tf32(acc[mt][nt], af[mt][0], af[mt][1], af[mt][2], af[mt][3],
                             bf[nt][0], bf[nt][1]);
        }
        __syncthreads();
    }

    #pragma unroll
    for (int nt = 0; nt < 4; nt++) {
        int n = bn + wn + nt * 8 + 2 * tg;
        float2 sc = make_float2(1.f, 1.f);
        if (cs) sc = *(const float2*)(cs + (size_t)b * HWIMG + n);
        #pragma unroll
        for (int mt = 0; mt < 4; mt++) {
            int m0 = bm + wm + mt * 16 + g;
            int m1 = m0 + 8;
            #pragma unroll
            for (int half_i = 0; half_i < 2; half_i++) {
                int m = half_i ? m1 : m0;
                if (m >= M) continue;
                size_t off = ((size_t)b * M + m) * HWIMG + n;
                float2 o = half_i
                    ? make_float2(acc[mt][nt][2] * sc.x, acc[mt][nt][3] * sc.y)
                    : make_float2(acc[mt][nt][0] * sc.x, acc[mt][nt][1] * sc.y);
                if (RESID) {
                    float2 r = *(const float2*)(R + off);
                    o.x += r.x; o.y += r.y;
                }
                if (Yf) *(float2*)(Yf + off) = o;
                if (Yh) *(__half2*)(Yh + off) = __floats2half2_rn(o.x, o.y);
            }
        }
    }
}

// ---------------- tiled depthwise 3x3 (fp16 I/O, fp32 smem tile pitch 80) ----------------
#define DWP2 80

__device__ __forceinline__ void dw_load_tile_h(const __half* __restrict__ ip,
                                               float* __restrict__ tile,
                                               int y0, int x0, int tid) {
    for (int i = tid; i < 34 * 10; i += 256) {
        int r = i / 10, k = i - r * 10;
        int gy = y0 - 1 + r;
        int gx = x0 - 8 + k * 8;
        float4 f01 = make_float4(0.f, 0.f, 0.f, 0.f), f23 = f01;
        if (gy >= 0 && gy < 256 && gx >= 0 && gx < 256) {
            uint4 v = *(const uint4*)(ip + gy * IMW + gx);
            float2 a = __half22float2(*(__half2*)&v.x);
            float2 bq = __half22float2(*(__half2*)&v.y);
            float2 c = __half22float2(*(__half2*)&v.z);
            float2 d = __half22float2(*(__half2*)&v.w);
            f01 = make_float4(a.x, a.y, bq.x, bq.y);
            f23 = make_float4(c.x, c.y, d.x, d.y);
        }
        *(float4*)&tile[r * DWP2 + k * 8]     = f01;
        *(float4*)&tile[r * DWP2 + k * 8 + 4] = f23;
    }
}

__device__ __forceinline__ void dw_compute8h(const float* __restrict__ tile,
                                             const float* __restrict__ wr,
                                             int row, int col0, float* o) {
    float r0[10], r1[10], r2[10];
    const float* t0 = tile + row * DWP2 + col0 + 7;
    #pragma unroll
    for (int j = 0; j < 10; j++) {
        r0[j] = t0[j];
        r1[j] = t0[DWP2 + j];
        r2[j] = t0[2 * DWP2 + j];
    }
    #pragma unroll
    for (int j = 0; j < 8; j++) {
        o[j] = r0[j] * wr[0] + r0[j+1] * wr[1] + r0[j+2] * wr[2]
             + r1[j] * wr[3] + r1[j+1] * wr[4] + r1[j+2] * wr[5]
             + r2[j] * wr[6] + r2[j+1] * wr[7] + r2[j+2] * wr[8];
    }
}

__device__ __forceinline__ void store8h(__half* op, const float* o) {
    uint4 v;
    *(__half2*)&v.x = __floats2half2_rn(o[0], o[1]);
    *(__half2*)&v.y = __floats2half2_rn(o[2], o[3]);
    *(__half2*)&v.z = __floats2half2_rn(o[4], o[5]);
    *(__half2*)&v.w = __floats2half2_rn(o[6], o[7]);
    *(uint4*)op = v;
}

__global__ void __launch_bounds__(256) dwconv_kernel(
        const __half* __restrict__ in, const float* __restrict__ w,
        __half* __restrict__ out, int C) {
    __shared__ float tile[34 * DWP2];
    int tid = threadIdx.x;
    int t   = blockIdx.x;
    int c   = blockIdx.y, b = blockIdx.z;
    int y0  = (t >> 2) * 32, x0 = (t & 3) * 64;

    const __half* ip = in + ((size_t)b * C + c) * HWIMG;
    dw_load_tile_h(ip, tile, y0, x0, tid);
    float wr[9];
    #pragma unroll
    for (int j = 0; j < 9; j++) wr[j] = w[c * 9 + j];
    __syncthreads();

    int row = tid >> 3, col0 = (tid & 7) * 8;
    float o[8];
    dw_compute8h(tile, wr, row, col0, o);
    store8h(out + ((size_t)b * C + c) * HWIMG + (y0 + row) * IMW + x0 + col0, o);
}

__global__ void __launch_bounds__(256) dwgate_kernel(
        const __half* __restrict__ in, const float* __restrict__ w,
        __half* __restrict__ gout) {
    __shared__ float tile1[34 * DWP2];
    __shared__ float tile2[34 * DWP2];
    int tid = threadIdx.x;
    int t   = blockIdx.x;
    int c   = blockIdx.y, b = blockIdx.z;
    int y0  = (t >> 2) * 32, x0 = (t & 3) * 64;

    const __half* ip1 = in + ((size_t)b * CHID2 + c) * HWIMG;
    const __half* ip2 = in + ((size_t)b * CHID2 + CHID + c) * HWIMG;
    dw_load_tile_h(ip1, tile1, y0, x0, tid);
    dw_load_tile_h(ip2, tile2, y0, x0, tid);
    float wr1[9], wr2[9];
    #pragma unroll
    for (int j = 0; j < 9; j++) {
        wr1[j] = w[c * 9 + j];
        wr2[j] = w[(CHID + c) * 9 + j];
    }
    __syncthreads();

    int row = tid >> 3, col0 = (tid & 7) * 8;
    float v1[8], v2[8];
    dw_compute8h(tile1, wr1, row, col0, v1);
    dw_compute8h(tile2, wr2, row, col0, v2);
    float o[8];
    #pragma unroll
    for (int j = 0; j < 8; j++) {
        float ge = 0.5f * v1[j] * (1.f + erff(v1[j] * 0.70710678118654752f));
        o[j] = ge * v2[j];
    }
    store8h(gout + ((size_t)b * CHID + c) * HWIMG + (y0 + row) * IMW + x0 + col0, o);
}

// ---------------- windowed FFT attention: all contractions MMA (fp16 I/O) ----------------
#define SM_DS  0
#define SM_SX  5376
#define SM_ATR 5376
#define SM_ATI 7616
#define SM_PT  9856
#define SM_QKT 15104
#define SM_VT  23168
#define SM_SC  27648
#define ATTN_SMEM_FLOATS 27688

__global__ void __launch_bounds__(256) attn_kernel(
        const __half* __restrict__ qkv, const float* __restrict__ temp,
        __half* __restrict__ outp) {
    extern __shared__ float sm[];
    uint32_t* Ds  = (uint32_t*)(sm + SM_DS);
    uint32_t* sx  = (uint32_t*)(sm + SM_SX);
    uint32_t* atr = (uint32_t*)(sm + SM_ATR);
    uint32_t* ati = (uint32_t*)(sm + SM_ATI);
    uint32_t* PT  = (uint32_t*)(sm + SM_PT);
    uint32_t* QKT = (uint32_t*)(sm + SM_QKT);
    uint32_t* VT  = (uint32_t*)(sm + SM_VT);
    float*    sc  = sm + SM_SC;

    int tid  = threadIdx.x;
    int warp = tid >> 5, lane = tid & 31;
    int g    = lane >> 2, tg = lane & 3;
    int wy   = blockIdx.x >> 5, wx = blockIdx.x & 31;
    int head = blockIdx.y, b = blockIdx.z;
    float tv = temp[head];

    size_t base = ((size_t)b * C6 + head * CH) * HWIMG + (size_t)(wy * 8) * IMW + wx * 8;

    for (int i = tid; i < 64 * 84; i += 256) Ds[i] = g_dft[i];
    for (int i = tid; i < 3 * CH * 64; i += 256) {
        int t = i / 3072, rem = i - t * 3072;
        int c = rem >> 6, n = rem & 63;
        __half v = qkv[base + (size_t)(t * C2 + c) * HWIMG + (n >> 3) * IMW + (n & 7)];
        sx[n * 152 + t * CH + c] = h2tf(v);
    }
    __syncthreads();

    // DFT
    for (int t8 = warp; t8 < 90; t8 += 8) {
        int mt = t8 / 18, nt = t8 % 18;
        int m0 = mt * 16, n0 = nt * 8;
        int mA = m0 + g, mB = mA + 8;
        int colA = (mA < 40) ? 2 * mA : 2 * (mA - 40) + 1;
        int colB = (mB < 40) ? 2 * mB : 2 * (mB - 40) + 1;
        float acc[4] = {0.f, 0.f, 0.f, 0.f};
        #pragma unroll
        for (int kc = 0; kc < 8; kc++) {
            int kb = kc * 8;
            uint32_t a0 = Ds[(kb + tg)     * 84 + colA];
            uint32_t a1 = Ds[(kb + tg)     * 84 + colB];
            uint32_t a2 = Ds[(kb + tg + 4) * 84 + colA];
            uint32_t a3 = Ds[(kb + tg + 4) * 84 + colB];
            uint32_t b0 = sx[(kb + tg)     * 152 + n0 + g];
            uint32_t b1 = sx[(kb + tg + 4) * 152 + n0 + g];
            mma_tf32(acc, a0, a1, a2, a3, b0, b1);
        }
        int c0 = n0 + 2 * tg;
        if (n0 < 96) {
            QKT[c0 * 84 + mA]       = f2tf(acc[0]);
            QKT[(c0 + 1) * 84 + mA] = f2tf(acc[1]);
            QKT[c0 * 84 + mB]       = f2tf(acc[2]);
            QKT[(c0 + 1) * 84 + mB] = f2tf(acc[3]);
        } else {
            int cv = c0 - 96;
            VT[mA * 56 + cv]     = f2tf(acc[0]);
            VT[mA * 56 + cv + 1] = f2tf(acc[1]);
            VT[mB * 56 + cv]     = f2tf(acc[2]);
            VT[mB * 56 + cv + 1] = f2tf(acc[3]);
        }
    }
    __syncthreads();

    // gram -> atT[g][f]
    for (int t8 = warp; t8 < 15; t8 += 8) {
        int mt = t8 / 5, nt = t8 % 5;
        int m0 = mt * 16, n0 = nt * 8;
        int fA = m0 + g, fB = fA + 8;
        int ciA = 40 + ((fA < 40) ? fA : 0);
        int ciB = 40 + ((fB < 40) ? fB : 0);
        float aR[4] = {0,0,0,0}, aI[4] = {0,0,0,0};
        #pragma unroll
        for (int kc = 0; kc < 6; kc++) {
            int kb = kc * 8;
            uint32_t qr0 = QKT[(kb + tg)     * 84 + fA];
            uint32_t qr1 = QKT[(kb + tg)     * 84 + fB];
            uint32_t qr2 = QKT[(kb + tg + 4) * 84 + fA];
            uint32_t qr3 = QKT[(kb + tg + 4) * 84 + fB];
            uint32_t qi0 = QKT[(kb + tg)     * 84 + ciA];
            uint32_t qi1 = QKT[(kb + tg)     * 84 + ciB];
            uint32_t qi2 = QKT[(kb + tg + 4) * 84 + ciA];
            uint32_t qi3 = QKT[(kb + tg + 4) * 84 + ciB];
            uint32_t kr0 = QKT[(48 + kb + tg)     * 84 + n0 + g];
            uint32_t kr1 = QKT[(48 + kb + tg + 4) * 84 + n0 + g];
            uint32_t ki0 = QKT[(48 + kb + tg)     * 84 + 40 + n0 + g];
            uint32_t ki1 = QKT[(48 + kb + tg + 4) * 84 + 40 + n0 + g];
            mma_tf32(aR, qr0, qr1, qr2, qr3, kr0, kr1);
            mma_tf32(aR, qi0, qi1, qi2, qi3, fneg(ki0), fneg(ki1));
            mma_tf32(aI, qr0, qr1, qr2, qr3, ki0, ki1);
            mma_tf32(aI, qi0, qi1, qi2, qi3, kr0, kr1);
        }
        int gc0 = n0 + 2 * tg, gc1 = gc0 + 1;
        atr[gc0 * 56 + fA] = f2tf(aR[0]);  ati[gc0 * 56 + fA] = f2tf(aI[0]);
        atr[gc1 * 56 + fA] = f2tf(aR[1]);  ati[gc1 * 56 + fA] = f2tf(aI[1]);
        atr[gc0 * 56 + fB] = f2tf(aR[2]);  ati[gc0 * 56 + fB] = f2tf(aI[2]);
        atr[gc1 * 56 + fB] = f2tf(aR[3]);  ati[gc1 * 56 + fB] = f2tf(aI[3]);
    }
    __syncthreads();

    // row norms + zero PT pad rows
    if (tid < NF) {
        float s = 0.f;
        #pragma unroll 3
        for (int g2 = 0; g2 < NF; g2++) {
            float ar = __uint_as_float(atr[g2 * 56 + tid]);
            float ai = __uint_as_float(ati[g2 * 56 + tid]);
            s += ar * ar + ai * ai;
        }
        float w = (tid == 0 || tid == 32) ? 1.f : 2.f;
        sc[tid] = copysignf(1.f, tv) * rsqrtf(s) * w * (1.f / 64.f);
    }
    for (int i = tid; i < 6 * 56; i += 256) PT[66 * 56 + i] = 0u;
    __syncthreads();

    // apply -> PT[2f][c]
    for (int t8 = warp; t8 < 18; t8 += 8) {
        int mt = t8 / 6, nt = t8 % 6;
        int m0 = mt * 16, n0 = nt * 8;
        float pR[4] = {0,0,0,0}, pI[4] = {0,0,0,0};
        #pragma unroll
        for (int kc = 0; kc < 5; kc++) {
            int kb = kc * 8;
            uint32_t vr0 = VT[(kb + tg)          * 56 + m0 + g];
            uint32_t vr1 = VT[(kb + tg)          * 56 + m0 + g + 8];
            uint32_t vr2 = VT[(kb + tg + 4)      * 56 + m0 + g];
            uint32_t vr3 = VT[(kb + tg + 4)      * 56 + m0 + g + 8];
            uint32_t vi0 = VT[(40 + kb + tg)     * 56 + m0 + g];
            uint32_t vi1 = VT[(40 + kb + tg)     * 56 + m0 + g + 8];
            uint32_t vi2 = VT[(40 + kb + tg + 4) * 56 + m0 + g];
            uint32_t vi3 = VT[(40 + kb + tg + 4) * 56 + m0 + g + 8];
            uint32_t bR0 = atr[(kb + tg)     * 56 + n0 + g];
            uint32_t bR1 = atr[(kb + tg + 4) * 56 + n0 + g];
            uint32_t bI0 = ati[(kb + tg)     * 56 + n0 + g];
            uint32_t bI1 = ati[(kb + tg + 4) * 56 + n0 + g];
            mma_tf32(pR, vr0, vr1, vr2, vr3, bR0, bR1);
            mma_tf32(pR, fneg(vi0), fneg(vi1), fneg(vi2), fneg(vi3), bI0, bI1);
            mma_tf32(pI, vr0, vr1, vr2, vr3, bI0, bI1);
            mma_tf32(pI, vi0, vi1, vi2, vi3, bR0, bR1);
        }
        int c0 = m0 + g, c1 = c0 + 8;
        int f0 = n0 + 2 * tg, f1 = f0 + 1;
        if (f0 < NF) {
            float s = sc[f0];
            PT[(2 * f0) * 56 + c0]     = f2tf(pR[0] * s);
            PT[(2 * f0 + 1) * 56 + c0] = f2tf(pI[0] * s);
            PT[(2 * f0) * 56 + c1]     = f2tf(pR[2] * s);
            PT[(2 * f0 + 1) * 56 + c1] = f2tf(pI[2] * s);
        }
        if (f1 < NF) {
            float s = sc[f1];
            PT[(2 * f1) * 56 + c0]     = f2tf(pR[1] * s);
            PT[(2 * f1 + 1) * 56 + c0] = f2tf(pI[1] * s);
            PT[(2 * f1) * 56 + c1]     = f2tf(pR[3] * s);
            PT[(2 * f1 + 1) * 56 + c1] = f2tf(pI[3] * s);
        }
    }
    __syncthreads();

    // irDFT -> fp16 stores
    __half* outBase = outp + ((size_t)b * C2 + head * CH) * HWIMG
                    + (size_t)(wy * 8) * IMW + wx * 8;
    for (int t8 = warp; t8 < 24; t8 += 8) {
        int mt = t8 / 8, nt = t8 % 8;
        int m0 = mt * 16, n0 = nt * 8;
        float acc[4] = {0.f, 0.f, 0.f, 0.f};
        #pragma unroll
        for (int kc = 0; kc < 9; kc++) {
            int kb = kc * 8;
            uint32_t a0 = PT[(kb + tg)     * 56 + m0 + g];
            uint32_t a1 = PT[(kb + tg)     * 56 + m0 + g + 8];
            uint32_t a2 = PT[(kb + tg + 4) * 56 + m0 + g];
            uint32_t a3 = PT[(kb + tg + 4) * 56 + m0 + g + 8];
            uint32_t b0 = Ds[(n0 + g) * 84 + kb + tg];
            uint32_t b1 = Ds[(n0 + g) * 84 + kb + tg + 4];
            mma_tf32(acc, a0, a1, a2, a3, b0, b1);
        }
        int c = m0 + g;
        *(__half2*)&outBase[(size_t)c       * HWIMG + nt * IMW + 2 * tg] =
            __floats2half2_rn(acc[0], acc[1]);
        *(__half2*)&outBase[(size_t)(c + 8) * HWIMG + nt * IMW + 2 * tg] =
            __floats2half2_rn(acc[2], acc[3]);
    }
}

// ---------------- launch ----------------
extern "C" void kernel_launch(void* const* d_in, const int* in_sizes, int n_in,
                              void* d_out, int out_size) {
    const float* x      = (const float*)d_in[0];
    const float* w_hid  = (const float*)d_in[1];
    const float* w_hdw  = (const float*)d_in[2];
    const float* w_proj = (const float*)d_in[3];
    const float* temp   = (const float*)d_in[4];
    const float* n1w    = (const float*)d_in[5];
    const float* n2w    = (const float*)d_in[6];
    const float* w_fin  = (const float*)d_in[7];
    const float* w_fdw  = (const float*)d_in[8];
    const float* w_fout = (const float*)d_in[9];
    float* out = (float*)d_out;

    __half *h1, *h2, *att, *x1h, *f1, *gg;
    float *x1, *inv;
    cudaGetSymbolAddress((void**)&h1,  g_h1);
    cudaGetSymbolAddress((void**)&h2,  g_h2);
    cudaGetSymbolAddress((void**)&att, g_att);
    cudaGetSymbolAddress((void**)&x1,  g_x1);
    cudaGetSymbolAddress((void**)&x1h, g_x1h);
    cudaGetSymbolAddress((void**)&f1,  g_f1);
    cudaGetSymbolAddress((void**)&gg,  g_g);
    cudaGetSymbolAddress((void**)&inv, g_inv);

    cudaFuncSetAttribute(attn_kernel, cudaFuncAttributeMaxDynamicSharedMemorySize,
                         ATTN_SMEM_FLOATS * 4);
    cudaFuncSetAttribute(gemm_tf32_kernel<false, false>,
                         cudaFuncAttributeMaxDynamicSharedMemorySize, GEMM_SMEM_BYTES);
    cudaFuncSetAttribute(gemm_tf32_kernel<false, true>,
                         cudaFuncAttributeMaxDynamicSharedMemorySize, GEMM_SMEM_BYTES);
    cudaFuncSetAttribute(gemm_tf32_kernel<true, true>,
                         cudaFuncAttributeMaxDynamicSharedMemorySize, GEMM_SMEM_BYTES);

    // 0) twiddle init
    dft_init_kernel<<<21, 256>>>();
    // 1) LN1 scale
    ln_scale_kernel<<<dim3(256, BDIM), 256>>>(x, inv);
    // 2) to_hidden 1x1 (96 -> 576), LN fused, fp16 out
    gemm_tf32_kernel<false, false><<<dim3(512, 5, BDIM), 256, GEMM_SMEM_BYTES>>>(
        w_hid, x, nullptr, n1w, inv, nullptr, h1, C6, CDIM);
    // 3) dwconv 3x3 (fp16 I/O)
    dwconv_kernel<<<dim3(32, C6, BDIM), 256>>>(h1, w_hdw, h2, C6);
    // 4) windowed FFT attention (fp16 I/O)
    attn_kernel<<<dim3(1024, HEADS, BDIM), 256, ATTN_SMEM_FLOATS * 4>>>(h2, temp, att);
    // 5) project_out 1x1 (192 -> 96) + residual x -> x1 (fp32) + x1h (fp16)
    gemm_tf32_kernel<true, true><<<dim3(512, 1, BDIM), 256, GEMM_SMEM_BYTES>>>(
        w_proj, att, x, nullptr, nullptr, x1, x1h, CDIM, C2);
    // 6) LN2 scale
    ln_scale_kernel<<<dim3(256, BDIM), 256>>>(x1, inv);
    // 7) ffn in 1x1 (96 -> 510), LN fused, fp16 in/out
    gemm_tf32_kernel<false, true><<<dim3(512, 4, BDIM), 256, GEMM_SMEM_BYTES>>>(
        w_fin, x1h, nullptr, n2w, inv, nullptr, f1, CHID2, CDIM);
    // 8) fused dwconv + gelu gate (fp16 I/O)
    dwgate_kernel<<<dim3(32, CHID, BDIM), 256>>>(f1, w_fdw, gg);
    // 9) ffn out 1x1 (255 -> 96) + residual x1 -> d_out (fp32)
    gemm_tf32_kernel<true, true><<<dim3(512, 1, BDIM), 256, GEMM_SMEM_BYTES>>>(
        w_fout, gg, x1, nullptr, nullptr, out, nullptr, CDIM, CHID);
}

// round 15
// speedup vs baseline: 1.2398x; 1.2398x over previous
#include <cuda_runtime.h>
#include <cuda_fp16.h>
#include <math.h>
#include <stdint.h>

// ---------------- problem constants ----------------
#define IMW   256
#define HWIMG 65536          // 256*256
#define BDIM  2
#define CDIM  96
#define C6    576            // 6*DIM
#define C2    192            // 2*DIM
#define CHID  255            // hidden_features
#define CHID2 510            // 2*hidden
#define HEADS 4
#define CH    48             // channels per head
#define NF    33             // rfft bins of 64

// ---------------- scratch (fp16 intermediates) ----------------
__device__ __half g_h1 [(size_t)BDIM * C6    * HWIMG];
__device__ __half g_h2 [(size_t)BDIM * C6    * HWIMG];
__device__ __half g_att[(size_t)BDIM * C2    * HWIMG];
__device__ float  g_x1 [(size_t)BDIM * CDIM  * HWIMG];
__device__ __half g_x1h[(size_t)BDIM * CDIM  * HWIMG];
__device__ __half g_f1 [(size_t)BDIM * CHID2 * HWIMG];
__device__ __half g_g  [(size_t)BDIM * CHID  * HWIMG];
__device__ float  g_inv[(size_t)BDIM * HWIMG];
__device__ __align__(16) __half g_dftA[80 * 72];  // EH[fcomp][t]: cos rows 0-39, -sin rows 40-79; t>=64 zero
__device__ __align__(16) __half g_dftB[64 * 80];  // DsN[n][col]: col 2f=cos, 2f+1=-sin, col>=66 zero

__device__ __forceinline__ uint32_t f2tf(float f) {
    uint32_t u;
    asm("cvt.rna.tf32.f32 %0, %1;" : "=r"(u) : "f"(f));
    return u;
}
__device__ __forceinline__ uint32_t h2tf(__half h) {
    return __float_as_uint(__half2float(h));
}
__device__ __forceinline__ uint32_t hneg2(uint32_t u) { return u ^ 0x80008000u; }

__device__ __forceinline__ void mma_tf32(float* d, uint32_t a0, uint32_t a1,
                                         uint32_t a2, uint32_t a3,
                                         uint32_t b0, uint32_t b1) {
    asm volatile(
        "mma.sync.aligned.m16n8k8.row.col.f32.tf32.tf32.f32 "
        "{%0,%1,%2,%3}, {%4,%5,%6,%7}, {%8,%9}, {%0,%1,%2,%3};\n"
        : "+f"(d[0]), "+f"(d[1]), "+f"(d[2]), "+f"(d[3])
        : "r"(a0), "r"(a1), "r"(a2), "r"(a3), "r"(b0), "r"(b1));
}

__device__ __forceinline__ void mma_f16(float* d, uint32_t a0, uint32_t a1,
                                        uint32_t a2, uint32_t a3,
                                        uint32_t b0, uint32_t b1) {
    asm volatile(
        "mma.sync.aligned.m16n8k16.row.col.f32.f16.f16.f32 "
        "{%0,%1,%2,%3}, {%4,%5,%6,%7}, {%8,%9}, {%0,%1,%2,%3};\n"
        : "+f"(d[0]), "+f"(d[1]), "+f"(d[2]), "+f"(d[3])
        : "r"(a0), "r"(a1), "r"(a2), "r"(a3), "r"(b0), "r"(b1));
}

__device__ __forceinline__ void cp_async16(uint32_t smem_addr, const void* gptr) {
    asm volatile("cp.async.cg.shared.global [%0], [%1], 16;\n"
                 :: "r"(smem_addr), "l"(gptr));
}

// ---------------- twiddle init (fp16, both layouts) ----------------
__global__ void dft_init_kernel() {
    int i = blockIdx.x * 256 + threadIdx.x;
    if (i < 80 * 72) {
        int r = i / 72, t = i % 72;
        float v = 0.f;
        if (t < 64) {
            int f = (r < 40) ? r : r - 40;
            float ang = 6.2831853071795864f * (float)((f * t) & 63) / 64.f;
            v = (r < 40) ? cosf(ang) : -sinf(ang);
        }
        g_dftA[i] = __float2half_rn(v);
    } else if (i < 80 * 72 + 64 * 80) {
        int j = i - 80 * 72;
        int n = j / 80, col = j % 80;
        float v = 0.f;
        if (col < 66) {
            int f = col >> 1;
            float ang = 6.2831853071795864f * (float)((f * n) & 63) / 64.f;
            v = (col & 1) ? -sinf(ang) : cosf(ang);
        }
        g_dftB[j] = __float2half_rn(v);
    }
}

// ---------------- LN scale only ----------------
__global__ void ln_scale_kernel(const float* __restrict__ x, float* __restrict__ inv) {
    int pix = blockIdx.x * 256 + threadIdx.x;
    int b   = blockIdx.y;
    const float* xb = x + (size_t)b * CDIM * HWIMG + pix;
    float s = 0.f, s2 = 0.f;
    #pragma unroll 8
    for (int c = 0; c < CDIM; c++) {
        float v = xb[(size_t)c * HWIMG];
        s += v; s2 += v * v;
    }
    float mean = s * (1.0f / CDIM);
    float var  = s2 * (1.0f / CDIM) - mean * mean;
    inv[(size_t)b * HWIMG + pix] = rsqrtf(var + 1e-5f);
}

// ---------------- tf32 conv1x1 GEMM (R13: cp.async double-buffered) ----------------
#define GBM 128
#define GBN 128
#define GBK 32
#define GPAD 8
#define GP   (GBM + GPAD)    // 136
#define AS(st,k,m)  Asb[((st) * GBK + (k)) * GP + (m)]
#define BS(st,k,n)  Bsb[((st) * GBK + (k)) * GP + (n)]
#define BSH(st,k,n) BsbH[((st) * GBK + (k)) * GP + (n)]
#define GEMM_SMEM_BYTES (2 * GBK * GP * 2 * 4)   // 69632

template<bool RESID, bool XHALF>
__global__ void __launch_bounds__(256) gemm_tf32_kernel(
        const float* __restrict__ A, const void* __restrict__ Xv,
        const float* __restrict__ R, const float* __restrict__ nw,
        const float* __restrict__ cs, float* __restrict__ Yf,
        __half* __restrict__ Yh, int M, int K) {
    extern __shared__ uint32_t gsm[];
    uint32_t* Asb  = gsm;
    uint32_t* Bsb  = gsm + 2 * GBK * GP;
    __half*   BsbH = (__half*)Bsb;

    int tid  = threadIdx.x;
    int warp = tid >> 5, lane = tid & 31;
    int g    = lane >> 2, tg = lane & 3;
    int wm   = (warp & 1) * 64;
    int wn   = (warp >> 1) * 32;

    int bn = blockIdx.x * GBN;
    int bm = blockIdx.y * GBM;
    int b  = blockIdx.z;
    const float*  Xf = XHALF ? nullptr : ((const float*)Xv + (size_t)b * K * HWIMG + bn);
    const __half* Xh = XHALF ? ((const __half*)Xv + (size_t)b * K * HWIMG + bn) : nullptr;

    float acc[4][4][4];
    #pragma unroll
    for (int mt = 0; mt < 4; mt++)
        #pragma unroll
        for (int nt = 0; nt < 4; nt++)
            #pragma unroll
            for (int i = 0; i < 4; i++) acc[mt][nt][i] = 0.f;

    int xk  = tid >> 3;
    int xc  = (tid & 7) * 4;
    int xch = (tid & 7) * 16;
    int nIter = (K + GBK - 1) / GBK;

    auto loadTiles = [&](int it, int st) {
        int k0 = it * GBK;
        #pragma unroll
        for (int i = 0; i < 16; i++) {
            int lin = tid + i * 256;
            int m = lin & 127, k = lin >> 7;
            int gm = bm + m, gk = k0 + k;
            float v = (gm < M && gk < K) ? A[(size_t)gm * K + gk] : 0.f;
            if (nw && gk < K) v *= nw[gk];
            AS(st, k, m) = f2tf(v);
        }
        int gk = k0 + xk;
        if (XHALF) {
            if (gk < K) {
                const __half* p = Xh + (size_t)gk * HWIMG + xch;
                uint32_t sa = (uint32_t)__cvta_generic_to_shared(&BSH(st, xk, xch));
                cp_async16(sa, p);
                cp_async16(sa + 16, p + 8);
            } else {
                uint4 z = make_uint4(0u, 0u, 0u, 0u);
                *(uint4*)&BSH(st, xk, xch)     = z;
                *(uint4*)&BSH(st, xk, xch + 8) = z;
            }
        } else {
            if (gk < K) {
                const float* p = Xf + (size_t)gk * HWIMG + xc;
                uint32_t sa = (uint32_t)__cvta_generic_to_shared(&BS(st, xk, xc));
                #pragma unroll
                for (int j = 0; j < 4; j++)
                    cp_async16(sa + j * 128, p + j * 32);
            } else {
                uint4 z = make_uint4(0u, 0u, 0u, 0u);
                #pragma unroll
                for (int j = 0; j < 4; j++)
                    *(uint4*)&BS(st, xk, xc + j * 32) = z;
            }
        }
    };

    loadTiles(0, 0);
    asm volatile("cp.async.commit_group;\n" ::: "memory");

    for (int it = 0; it < nIter; it++) {
        int st = it & 1;
        if (it + 1 < nIter) {
            loadTiles(it + 1, st ^ 1);
            asm volatile("cp.async.commit_group;\n" ::: "memory");
            asm volatile("cp.async.wait_group 1;\n" ::: "memory");
        } else {
            asm volatile("cp.async.wait_group 0;\n" ::: "memory");
        }
        __syncthreads();

        #pragma unroll
        for (int ks = 0; ks < 4; ks++) {
            int kb = ks * 8;
            uint32_t af[4][4], bf[4][2];
            #pragma unroll
            for (int mt = 0; mt < 4; mt++) {
                int m0 = wm + mt * 16;
                af[mt][0] = AS(st, kb + tg,     m0 + g);
                af[mt][1] = AS(st, kb + tg,     m0 + g + 8);
                af[mt][2] = AS(st, kb + tg + 4, m0 + g);
                af[mt][3] = AS(st, kb + tg + 4, m0 + g + 8);
            }
            #pragma unroll
            for (int nt = 0; nt < 4; nt++) {
                int n0 = wn + nt * 8;
                if (XHALF) {
                    bf[nt][0] = h2tf(BSH(st, kb + tg,     n0 + g));
                    bf[nt][1] = h2tf(BSH(st, kb + tg + 4, n0 + g));
                } else {
                    bf[nt][0] = BS(st, kb + tg,     n0 + g);
                    bf[nt][1] = BS(st, kb + tg + 4, n0 + g);
                }
            }
            #pragma unroll
            for (int mt = 0; mt < 4; mt++)
                #pragma unroll
                for (int nt = 0; nt < 4; nt++)
                    mma_tf32(acc[mt][nt], af[mt][0], af[mt][1], af[mt][2], af[mt][3],
                             bf[nt][0], bf[nt][1]);
        }
        __syncthreads();
    }

    #pragma unroll
    for (int nt = 0; nt < 4; nt++) {
        int n = bn + wn + nt * 8 + 2 * tg;
        float2 sc = make_float2(1.f, 1.f);
        if (cs) sc = *(const float2*)(cs + (size_t)b * HWIMG + n);
        #pragma unroll
        for (int mt = 0; mt < 4; mt++) {
            int m0 = bm + wm + mt * 16 + g;
            int m1 = m0 + 8;
            #pragma unroll
            for (int half_i = 0; half_i < 2; half_i++) {
                int m = half_i ? m1 : m0;
                if (m >= M) continue;
                size_t off = ((size_t)b * M + m) * HWIMG + n;
                float2 o = half_i
                    ? make_float2(acc[mt][nt][2] * sc.x, acc[mt][nt][3] * sc.y)
                    : make_float2(acc[mt][nt][0] * sc.x, acc[mt][nt][1] * sc.y);
                if (RESID) {
                    float2 r = *(const float2*)(R + off);
                    o.x += r.x; o.y += r.y;
                }
                if (Yf) *(float2*)(Yf + off) = o;
                if (Yh) *(__half2*)(Yh + off) = __floats2half2_rn(o.x, o.y);
            }
        }
    }
}

// ---------------- tiled depthwise 3x3 (fp16 I/O, fp32 smem tile pitch 80) ----------------
#define DWP2 80

__device__ __forceinline__ void dw_load_tile_h(const __half* __restrict__ ip,
                                               float* __restrict__ tile,
                                               int y0, int x0, int tid) {
    for (int i = tid; i < 34 * 10; i += 256) {
        int r = i / 10, k = i - r * 10;
        int gy = y0 - 1 + r;
        int gx = x0 - 8 + k * 8;
        float4 f01 = make_float4(0.f, 0.f, 0.f, 0.f), f23 = f01;
        if (gy >= 0 && gy < 256 && gx >= 0 && gx < 256) {
            uint4 v = *(const uint4*)(ip + gy * IMW + gx);
            float2 a = __half22float2(*(__half2*)&v.x);
            float2 bq = __half22float2(*(__half2*)&v.y);
            float2 c = __half22float2(*(__half2*)&v.z);
            float2 d = __half22float2(*(__half2*)&v.w);
            f01 = make_float4(a.x, a.y, bq.x, bq.y);
            f23 = make_float4(c.x, c.y, d.x, d.y);
        }
        *(float4*)&tile[r * DWP2 + k * 8]     = f01;
        *(float4*)&tile[r * DWP2 + k * 8 + 4] = f23;
    }
}

__device__ __forceinline__ void dw_compute8h(const float* __restrict__ tile,
                                             const float* __restrict__ wr,
                                             int row, int col0, float* o) {
    float r0[10], r1[10], r2[10];
    const float* t0 = tile + row * DWP2 + col0 + 7;
    #pragma unroll
    for (int j = 0; j < 10; j++) {
        r0[j] = t0[j];
        r1[j] = t0[DWP2 + j];
        r2[j] = t0[2 * DWP2 + j];
    }
    #pragma unroll
    for (int j = 0; j < 8; j++) {
        o[j] = r0[j] * wr[0] + r0[j+1] * wr[1] + r0[j+2] * wr[2]
             + r1[j] * wr[3] + r1[j+1] * wr[4] + r1[j+2] * wr[5]
             + r2[j] * wr[6] + r2[j+1] * wr[7] + r2[j+2] * wr[8];
    }
}

__device__ __forceinline__ void store8h(__half* op, const float* o) {
    uint4 v;
    *(__half2*)&v.x = __floats2half2_rn(o[0], o[1]);
    *(__half2*)&v.y = __floats2half2_rn(o[2], o[3]);
    *(__half2*)&v.z = __floats2half2_rn(o[4], o[5]);
    *(__half2*)&v.w = __floats2half2_rn(o[6], o[7]);
    *(uint4*)op = v;
}

__global__ void __launch_bounds__(256) dwconv_kernel(
        const __half* __restrict__ in, const float* __restrict__ w,
        __half* __restrict__ out, int C) {
    __shared__ float tile[34 * DWP2];
    int tid = threadIdx.x;
    int t   = blockIdx.x;
    int c   = blockIdx.y, b = blockIdx.z;
    int y0  = (t >> 2) * 32, x0 = (t & 3) * 64;

    const __half* ip = in + ((size_t)b * C + c) * HWIMG;
    dw_load_tile_h(ip, tile, y0, x0, tid);
    float wr[9];
    #pragma unroll
    for (int j = 0; j < 9; j++) wr[j] = w[c * 9 + j];
    __syncthreads();

    int row = tid >> 3, col0 = (tid & 7) * 8;
    float o[8];
    dw_compute8h(tile, wr, row, col0, o);
    store8h(out + ((size_t)b * C + c) * HWIMG + (y0 + row) * IMW + x0 + col0, o);
}

__global__ void __launch_bounds__(256) dwgate_kernel(
        const __half* __restrict__ in, const float* __restrict__ w,
        __half* __restrict__ gout) {
    __shared__ float tile1[34 * DWP2];
    __shared__ float tile2[34 * DWP2];
    int tid = threadIdx.x;
    int t   = blockIdx.x;
    int c   = blockIdx.y, b = blockIdx.z;
    int y0  = (t >> 2) * 32, x0 = (t & 3) * 64;

    const __half* ip1 = in + ((size_t)b * CHID2 + c) * HWIMG;
    const __half* ip2 = in + ((size_t)b * CHID2 + CHID + c) * HWIMG;
    dw_load_tile_h(ip1, tile1, y0, x0, tid);
    dw_load_tile_h(ip2, tile2, y0, x0, tid);
    float wr1[9], wr2[9];
    #pragma unroll
    for (int j = 0; j < 9; j++) {
        wr1[j] = w[c * 9 + j];
        wr2[j] = w[(CHID + c) * 9 + j];
    }
    __syncthreads();

    int row = tid >> 3, col0 = (tid & 7) * 8;
    float v1[8], v2[8];
    dw_compute8h(tile1, wr1, row, col0, v1);
    dw_compute8h(tile2, wr2, row, col0, v2);
    float o[8];
    #pragma unroll
    for (int j = 0; j < 8; j++) {
        float ge = 0.5f * v1[j] * (1.f + erff(v1[j] * 0.70710678118654752f));
        o[j] = ge * v2[j];
    }
    store8h(gout + ((size_t)b * CHID + c) * HWIMG + (y0 + row) * IMW + x0 + col0, o);
}

// ---------------- windowed FFT attention: fp16 m16n8k16 MMA everywhere ----------------
// half offsets (pitches chosen conflict-free mod 32 banks)
#define H_EH   0          // EH[fcomp<80][t], pitch 72
#define H_DSN  5760       // DsN[n<64][col], pitch 80 (cols>=66 zero)
#define H_SX   10880      // sxT[ch<144][t], pitch 72
#define H_ATR  10880      //   overlay: atR[f<40][g], pitch 56
#define H_ATI  13120      //   overlay: atI
#define H_PC   15360      //   overlay: PC[c<48][fcomp], pitch 88
#define H_QTR  21248      // QTr[f<40][c], pitch 56
#define H_QTI  23488
#define H_KTR  25728
#define H_KTI  27968
#define H_VR   30208      // VR[c<48][g], pitch 56 (cols 40-47 zeroed)
#define H_VI   32896
#define H_END  35584
#define SC_F   (H_END / 2)                 // 17792 floats
#define ATTN_SMEM_FLOATS (SC_F + 40)       // 17832 floats = 71328 B -> 3 CTAs/SM

#define LDH2(idx) (*(const uint32_t*)(sh + (idx)))

__global__ void __launch_bounds__(256) attn_kernel(
        const __half* __restrict__ qkv, const float* __restrict__ temp,
        __half* __restrict__ outp) {
    extern __shared__ float sm[];
    __half* sh = (__half*)sm;
    float*  sc = sm + SC_F;

    int tid  = threadIdx.x;
    int warp = tid >> 5, lane = tid & 31;
    int g    = lane >> 2, tg = lane & 3;
    int wy   = blockIdx.x >> 5, wx = blockIdx.x & 31;
    int head = blockIdx.y, b = blockIdx.z;
    float tv = temp[head];

    size_t base = ((size_t)b * C6 + head * CH) * HWIMG + (size_t)(wy * 8) * IMW + wx * 8;

    // ---- phase 1: twiddles + window + VR/VI pad-zero ----
    {
        const uint4* sA = (const uint4*)g_dftA;
        uint4* dA = (uint4*)(sh + H_EH);
        for (int i = tid; i < 720; i += 256) dA[i] = sA[i];
        const uint4* sB = (const uint4*)g_dftB;
        uint4* dB = (uint4*)(sh + H_DSN);
        for (int i = tid; i < 640; i += 256) dB[i] = sB[i];
        for (int i = tid; i < 144 * 8; i += 256) {
            int ch = i >> 3, py = i & 7;
            int t = ch / 48, c = ch - t * 48;
            const __half* p = qkv + base + (size_t)(t * C2 + c) * HWIMG + py * IMW;
            *(uint4*)(sh + H_SX + ch * 72 + py * 8) = *(const uint4*)p;
        }
        for (int i = tid; i < 384; i += 256) {   // zero VR/VI cols 40..47
            int mat = i / 192, r = (i % 192) / 4, j = i & 3;
            ((uint32_t*)(sh + (mat ? H_VI : H_VR) + r * 56 + 40))[j] = 0u;
        }
    }
    __syncthreads();

    // ---- phase 2: DFT  QFT[fcomp][c] = sum_t EH[fcomp][t] * sxT[c][t] ----
    for (int t8 = warp; t8 < 90; t8 += 8) {
        int mt = t8 / 18, nt = t8 % 18;
        int m0 = mt * 16, n0 = nt * 8;
        float acc[4] = {0.f, 0.f, 0.f, 0.f};
        #pragma unroll
        for (int kc = 0; kc < 4; kc++) {
            int kb = kc * 16;
            uint32_t a0 = LDH2(H_EH + (m0 + g)     * 72 + kb + 2 * tg);
            uint32_t a1 = LDH2(H_EH + (m0 + g + 8) * 72 + kb + 2 * tg);
            uint32_t a2 = LDH2(H_EH + (m0 + g)     * 72 + kb + 2 * tg + 8);
            uint32_t a3 = LDH2(H_EH + (m0 + g + 8) * 72 + kb + 2 * tg + 8);
            uint32_t b0 = LDH2(H_SX + (n0 + g) * 72 + kb + 2 * tg);
            uint32_t b1 = LDH2(H_SX + (n0 + g) * 72 + kb + 2 * tg + 8);
            mma_f16(acc, a0, a1, a2, a3, b0, b1);
        }
        int c0 = n0 + 2 * tg;
        int rA = m0 + g, rB = rA + 8;
        __half2 vA = __floats2half2_rn(acc[0], acc[1]);
        __half2 vB = __floats2half2_rn(acc[2], acc[3]);
        if (c0 < 48) {
            *(__half2*)(sh + ((rA < 40) ? H_QTR + rA * 56 : H_QTI + (rA - 40) * 56) + c0) = vA;
            *(__half2*)(sh + ((rB < 40) ? H_QTR + rB * 56 : H_QTI + (rB - 40) * 56) + c0) = vB;
        } else if (c0 < 96) {
            int cc = c0 - 48;
            *(__half2*)(sh + ((rA < 40) ? H_KTR + rA * 56 : H_KTI + (rA - 40) * 56) + cc) = vA;
            *(__half2*)(sh + ((rB < 40) ? H_KTR + rB * 56 : H_KTI + (rB - 40) * 56) + cc) = vB;
        } else {
            int cc = c0 - 96;
            int bA = (rA < 40) ? H_VR : H_VI;  int colA = (rA < 40) ? rA : rA - 40;
            int bB = (rB < 40) ? H_VR : H_VI;  int colB = (rB < 40) ? rB : rB - 40;
            sh[bA + cc * 56 + colA]       = __float2half_rn(acc[0]);
            sh[bA + (cc + 1) * 56 + colA] = __float2half_rn(acc[1]);
            sh[bB + cc * 56 + colB]       = __float2half_rn(acc[2]);
            sh[bB + (cc + 1) * 56 + colB] = __float2half_rn(acc[3]);
        }
    }
    __syncthreads();

    // ---- phase 3: gram  at[f][g] = sum_c QF[c][f]*KF[c][g] ----
    for (int t8 = warp; t8 < 15; t8 += 8) {
        int mt = t8 / 5, nt = t8 % 5;
        int m0 = mt * 16, n0 = nt * 8;
        float aR[4] = {0,0,0,0}, aI[4] = {0,0,0,0};
        #pragma unroll
        for (int kc = 0; kc < 3; kc++) {
            int kb = kc * 16;
            uint32_t qr0 = LDH2(H_QTR + (m0 + g)     * 56 + kb + 2 * tg);
            uint32_t qr1 = LDH2(H_QTR + (m0 + g + 8) * 56 + kb + 2 * tg);
            uint32_t qr2 = LDH2(H_QTR + (m0 + g)     * 56 + kb + 2 * tg + 8);
            uint32_t qr3 = LDH2(H_QTR + (m0 + g + 8) * 56 + kb + 2 * tg + 8);
            uint32_t qi0 = LDH2(H_QTI + (m0 + g)     * 56 + kb + 2 * tg);
            uint32_t qi1 = LDH2(H_QTI + (m0 + g + 8) * 56 + kb + 2 * tg);
            uint32_t qi2 = LDH2(H_QTI + (m0 + g)     * 56 + kb + 2 * tg + 8);
            uint32_t qi3 = LDH2(H_QTI + (m0 + g + 8) * 56 + kb + 2 * tg + 8);
            uint32_t kr0 = LDH2(H_KTR + (n0 + g) * 56 + kb + 2 * tg);
            uint32_t kr1 = LDH2(H_KTR + (n0 + g) * 56 + kb + 2 * tg + 8);
            uint32_t ki0 = LDH2(H_KTI + (n0 + g) * 56 + kb + 2 * tg);
            uint32_t ki1 = LDH2(H_KTI + (n0 + g) * 56 + kb + 2 * tg + 8);
            mma_f16(aR, qr0, qr1, qr2, qr3, kr0, kr1);
            mma_f16(aR, qi0, qi1, qi2, qi3, hneg2(ki0), hneg2(ki1));
            mma_f16(aI, qr0, qr1, qr2, qr3, ki0, ki1);
            mma_f16(aI, qi0, qi1, qi2, qi3, kr0, kr1);
        }
        int fA = m0 + g, fB = fA + 8;
        int gc = n0 + 2 * tg;
        if (fA < NF) {
            *(__half2*)(sh + H_ATR + fA * 56 + gc) = __floats2half2_rn(aR[0], aR[1]);
            *(__half2*)(sh + H_ATI + fA * 56 + gc) = __floats2half2_rn(aI[0], aI[1]);
        }
        if (fB < NF) {
            *(__half2*)(sh + H_ATR + fB * 56 + gc) = __floats2half2_rn(aR[2], aR[3]);
            *(__half2*)(sh + H_ATI + fB * 56 + gc) = __floats2half2_rn(aI[2], aI[3]);
        }
    }
    __syncthreads();

    // ---- phase 4: norms -> sc[f]; zero at pads (g 33..47) and PC pads (col 66..79) ----
    if (tid < NF) {
        float s = 0.f;
        #pragma unroll 3
        for (int g2 = 0; g2 < NF; g2++) {
            float ar = __half2float(sh[H_ATR + tid * 56 + g2]);
            float ai = __half2float(sh[H_ATI + tid * 56 + g2]);
            s += ar * ar + ai * ai;
        }
        float w = (tid == 0 || tid == 32) ? 1.f : 2.f;
        sc[tid] = copysignf(1.f, tv) * rsqrtf(s) * w * (1.f / 64.f);
    }
    for (int i = tid; i < 40 * 15 * 2; i += 256) {
        int mat = i / 600, r = (i % 600) / 15, cq = 33 + (i % 15);
        sh[(mat ? H_ATI : H_ATR) + r * 56 + cq] = __float2half_rn(0.f);
    }
    for (int i = tid; i < 48 * 14; i += 256) {
        int r = i / 14, cq = 66 + (i % 14);
        sh[H_PC + r * 88 + cq] = __float2half_rn(0.f);
    }
    __syncthreads();

    // ---- phase 5: apply  P[c][f] = sum_g V[c][g]*at[f][g] -> PC[c][2f..] ----
    for (int t8 = warp; t8 < 15; t8 += 8) {
        int mt = t8 / 5, nt = t8 % 5;
        int m0 = mt * 16, n0 = nt * 8;
        float pR[4] = {0,0,0,0}, pI[4] = {0,0,0,0};
        #pragma unroll
        for (int kc = 0; kc < 3; kc++) {
            int kb = kc * 16;
            uint32_t vr0 = LDH2(H_VR + (m0 + g)     * 56 + kb + 2 * tg);
            uint32_t vr1 = LDH2(H_VR + (m0 + g + 8) * 56 + kb + 2 * tg);
            uint32_t vr2 = LDH2(H_VR + (m0 + g)     * 56 + kb + 2 * tg + 8);
            uint32_t vr3 = LDH2(H_VR + (m0 + g + 8) * 56 + kb + 2 * tg + 8);
            uint32_t vi0 = LDH2(H_VI + (m0 + g)     * 56 + kb + 2 * tg);
            uint32_t vi1 = LDH2(H_VI + (m0 + g + 8) * 56 + kb + 2 * tg);
            uint32_t vi2 = LDH2(H_VI + (m0 + g)     * 56 + kb + 2 * tg + 8);
            uint32_t vi3 = LDH2(H_VI + (m0 + g + 8) * 56 + kb + 2 * tg + 8);
            uint32_t bR0 = LDH2(H_ATR + (n0 + g) * 56 + kb + 2 * tg);
            uint32_t bR1 = LDH2(H_ATR + (n0 + g) * 56 + kb + 2 * tg + 8);
            uint32_t bI0 = LDH2(H_ATI + (n0 + g) * 56 + kb + 2 * tg);
            uint32_t bI1 = LDH2(H_ATI + (n0 + g) * 56 + kb + 2 * tg + 8);
            mma_f16(pR, vr0, vr1, vr2, vr3, bR0, bR1);
            mma_f16(pR, hneg2(vi0), hneg2(vi1), hneg2(vi2), hneg2(vi3), bI0, bI1);
            mma_f16(pI, vr0, vr1, vr2, vr3, bI0, bI1);
            mma_f16(pI, vi0, vi1, vi2, vi3, bR0, bR1);
        }
        int c0 = m0 + g, c1 = c0 + 8;
        int f0 = n0 + 2 * tg, f1 = f0 + 1;
        if (f0 < NF) {
            float s = sc[f0];
            *(__half2*)(sh + H_PC + c0 * 88 + 2 * f0) = __floats2half2_rn(pR[0] * s, pI[0] * s);
            *(__half2*)(sh + H_PC + c1 * 88 + 2 * f0) = __floats2half2_rn(pR[2] * s, pI[2] * s);
        }
        if (f1 < NF) {
            float s = sc[f1];
            *(__half2*)(sh + H_PC + c0 * 88 + 2 * f1) = __floats2half2_rn(pR[1] * s, pI[1] * s);
            *(__half2*)(sh + H_PC + c1 * 88 + 2 * f1) = __floats2half2_rn(pR[3] * s, pI[3] * s);
        }
    }
    __syncthreads();

    // ---- phase 6: irDFT  out[c][n] = sum_col PC[c][col] * DsN[n][col] ----
    __half* outBase = outp + ((size_t)b * C2 + head * CH) * HWIMG
                    + (size_t)(wy * 8) * IMW + wx * 8;
    for (int t8 = warp; t8 < 24; t8 += 8) {
        int mt = t8 / 8, nt = t8 % 8;
        int m0 = mt * 16, n0 = nt * 8;
        float acc[4] = {0.f, 0.f, 0.f, 0.f};
        #pragma unroll
        for (int kc = 0; kc < 5; kc++) {
            int kb = kc * 16;
            uint32_t a0 = LDH2(H_PC + (m0 + g)     * 88 + kb + 2 * tg);
            uint32_t a1 = LDH2(H_PC + (m0 + g + 8) * 88 + kb + 2 * tg);
            uint32_t a2 = LDH2(H_PC + (m0 + g)     * 88 + kb + 2 * tg + 8);
            uint32_t a3 = LDH2(H_PC + (m0 + g + 8) * 88 + kb + 2 * tg + 8);
            uint32_t b0 = LDH2(H_DSN + (n0 + g) * 80 + kb + 2 * tg);
            uint32_t b1 = LDH2(H_DSN + (n0 + g) * 80 + kb + 2 * tg + 8);
            mma_f16(acc, a0, a1, a2, a3, b0, b1);
        }
        int c = m0 + g;
        *(__half2*)&outBase[(size_t)c       * HWIMG + nt * IMW + 2 * tg] =
            __floats2half2_rn(acc[0], acc[1]);
        *(__half2*)&outBase[(size_t)(c + 8) * HWIMG + nt * IMW + 2 * tg] =
            __floats2half2_rn(acc[2], acc[3]);
    }
}

// ---------------- launch ----------------
extern "C" void kernel_launch(void* const* d_in, const int* in_sizes, int n_in,
                              void* d_out, int out_size) {
    const float* x      = (const float*)d_in[0];
    const float* w_hid  = (const float*)d_in[1];
    const float* w_hdw  = (const float*)d_in[2];
    const float* w_proj = (const float*)d_in[3];
    const float* temp   = (const float*)d_in[4];
    const float* n1w    = (const float*)d_in[5];
    const float* n2w    = (const float*)d_in[6];
    const float* w_fin  = (const float*)d_in[7];
    const float* w_fdw  = (const float*)d_in[8];
    const float* w_fout = (const float*)d_in[9];
    float* out = (float*)d_out;

    __half *h1, *h2, *att, *x1h, *f1, *gg;
    float *x1, *inv;
    cudaGetSymbolAddress((void**)&h1,  g_h1);
    cudaGetSymbolAddress((void**)&h2,  g_h2);
    cudaGetSymbolAddress((void**)&att, g_att);
    cudaGetSymbolAddress((void**)&x1,  g_x1);
    cudaGetSymbolAddress((void**)&x1h, g_x1h);
    cudaGetSymbolAddress((void**)&f1,  g_f1);
    cudaGetSymbolAddress((void**)&gg,  g_g);
    cudaGetSymbolAddress((void**)&inv, g_inv);

    cudaFuncSetAttribute(attn_kernel, cudaFuncAttributeMaxDynamicSharedMemorySize,
                         ATTN_SMEM_FLOATS * 4);
    cudaFuncSetAttribute(gemm_tf32_kernel<false, false>,
                         cudaFuncAttributeMaxDynamicSharedMemorySize, GEMM_SMEM_BYTES);
    cudaFuncSetAttribute(gemm_tf32_kernel<false, true>,
                         cudaFuncAttributeMaxDynamicSharedMemorySize, GEMM_SMEM_BYTES);
    cudaFuncSetAttribute(gemm_tf32_kernel<true, true>,
                         cudaFuncAttributeMaxDynamicSharedMemorySize, GEMM_SMEM_BYTES);

    // 0) twiddle init (both fp16 tables)
    dft_init_kernel<<<43, 256>>>();
    // 1) LN1 scale
    ln_scale_kernel<<<dim3(256, BDIM), 256>>>(x, inv);
    // 2) to_hidden 1x1 (96 -> 576), LN fused, fp16 out
    gemm_tf32_kernel<false, false><<<dim3(512, 5, BDIM), 256, GEMM_SMEM_BYTES>>>(
        w_hid, x, nullptr, n1w, inv, nullptr, h1, C6, CDIM);
    // 3) dwconv 3x3 (fp16 I/O)
    dwconv_kernel<<<dim3(32, C6, BDIM), 256>>>(h1, w_hdw, h2, C6);
    // 4) windowed FFT attention (fp16 MMA)
    attn_kernel<<<dim3(1024, HEADS, BDIM), 256, ATTN_SMEM_FLOATS * 4>>>(h2, temp, att);
    // 5) project_out 1x1 (192 -> 96) + residual x -> x1 (fp32) + x1h (fp16)
    gemm_tf32_kernel<true, true><<<dim3(512, 1, BDIM), 256, GEMM_SMEM_BYTES>>>(
        w_proj, att, x, nullptr, nullptr, x1, x1h, CDIM, C2);
    // 6) LN2 scale
    ln_scale_kernel<<<dim3(256, BDIM), 256>>>(x1, inv);
    // 7) ffn in 1x1 (96 -> 510), LN fused, fp16 in/out
    gemm_tf32_kernel<false, true><<<dim3(512, 4, BDIM), 256, GEMM_SMEM_BYTES>>>(
        w_fin, x1h, nullptr, n2w, inv, nullptr, f1, CHID2, CDIM);
    // 8) fused dwconv + gelu gate (fp16 I/O)
    dwgate_kernel<<<dim3(32, CHID, BDIM), 256>>>(f1, w_fdw, gg);
    // 9) ffn out 1x1 (255 -> 96) + residual x1 -> d_out (fp32)
    gemm_tf32_kernel<true, true><<<dim3(512, 1, BDIM), 256, GEMM_SMEM_BYTES>>>(
        w_fout, gg, x1, nullptr, nullptr, out, nullptr, CDIM, CHID);
}